// round 11
// baseline (speedup 1.0000x reference)
#include <cuda_runtime.h>
#include <cuda_bf16.h>

typedef __nv_bfloat16 bf16;
typedef unsigned int u32;

// Arena layout (bytes): xavgT f32 @0, xsumT f32 @4194304, xavh/xavl/xsmh/xsml
// bf16 @8388608/10485760/12582912/14680064, weight hi/lo bf16 @16777216..19398656
// (step 524288), Qh/Ql/Kh/Kl/VTh/VTl bf16 @19922944..30408704 (step 2097152),
// Lf f32 @32505856, Lh/Ll bf16 @34603008/35651584, OS f32 @36700160. End 40894464.
__device__ __align__(128) unsigned char g_arena[40894464];

__device__ __forceinline__ void ldsm4(u32& r0, u32& r1, u32& r2, u32& r3, u32 addr)
{
    asm volatile("ldmatrix.sync.aligned.m8n8.x4.shared.b16 { %0, %1, %2, %3 }, [%4];"
                 : "=r"(r0), "=r"(r1), "=r"(r2), "=r"(r3) : "r"(addr));
}

__device__ __forceinline__ void mma16816(float& d0, float& d1, float& d2, float& d3,
                                         u32 a0, u32 a1, u32 a2, u32 a3,
                                         u32 b0, u32 b1)
{
    asm volatile("mma.sync.aligned.m16n8k16.row.col.f32.bf16.bf16.f32 "
                 "{ %0, %1, %2, %3 }, { %4, %5, %6, %7 }, { %8, %9 }, { %0, %1, %2, %3 };"
                 : "+f"(d0), "+f"(d1), "+f"(d2), "+f"(d3)
                 : "r"(a0), "r"(a1), "r"(a2), "r"(a3), "r"(b0), "r"(b1));
}

__device__ __forceinline__ void cpa16(u32 dst, const bf16* src)
{
    asm volatile("cp.async.cg.shared.global [%0], [%1], 16;" :: "r"(dst), "l"(src));
}

__device__ __forceinline__ void cpa_commit()
{
    asm volatile("cp.async.commit_group;" ::: "memory");
}

__device__ __forceinline__ void cpa_wait1()
{
    asm volatile("cp.async.wait_group 1;" ::: "memory");
}

__device__ __forceinline__ void cpa_wait_all()
{
    asm volatile("cp.async.wait_group 0;" ::: "memory");
}

// Stage layout helper: [stage][split][row 0..63][40 bf16]  (padding 40 -> 80B rows)
__device__ __forceinline__ int soff(int st, int s, int r)
{
    return ((st * 2 + s) * 64 + r) * 40;
}

// ---------------------------------------------------------------------------
// Split-bf16 NT GEMM core: C = alpha*(Ahi+Alo)(Bhi+Blo)^T (+bias), lo*lo dropped.
// Tile 64x64, BK=32, 128 threads (4 warps 2x2), warp tile 32x32.
// 3-stage cp.async pipeline in dynamic shared memory (61440 bytes).
// ---------------------------------------------------------------------------
__device__ __forceinline__ void gemm_core(
    bf16* sm,
    const bf16* Ah, const bf16* Al, const bf16* Bh, const bf16* Bl,
    float* Cf, bf16* Ch, bf16* Cl,
    int K, int lda, int ldb, int ldc, int i0, int j0,
    float alpha, const float* bias, float biasScale, int biasMode)
{
    bf16* As = sm;             // 3*2*64*40 = 15360 elems
    bf16* Bs = sm + 15360;     // 15360 elems

    const int t = threadIdx.x;
    const int lane = t & 31;
    const int wid = t >> 5;
    const int wm = (wid >> 1) * 32;
    const int wn = (wid & 1) * 32;

    float acc[2][4][4];
#pragma unroll
    for (int a = 0; a < 2; a++) {
#pragma unroll
        for (int b = 0; b < 4; b++) {
            acc[a][b][0] = 0.f;
            acc[a][b][1] = 0.f;
            acc[a][b][2] = 0.f;
            acc[a][b][3] = 0.f;
        }
    }

    const int lr = t >> 2;          // 0..31
    const int lk = (t & 3) * 8;     // 0,8,16,24

    // prologue: stages 0 and 1 (k = 0, 32); K >= 64 always here
#pragma unroll
    for (int p = 0; p < 2; p++) {
        int kk = p * 32;
#pragma unroll
        for (int i = 0; i < 2; i++) {
            int r = lr + 32 * i;
            cpa16((u32)__cvta_generic_to_shared(&As[soff(p, 0, r) + lk]),
                  Ah + (size_t)(i0 + r) * lda + kk + lk);
            cpa16((u32)__cvta_generic_to_shared(&As[soff(p, 1, r) + lk]),
                  Al + (size_t)(i0 + r) * lda + kk + lk);
            cpa16((u32)__cvta_generic_to_shared(&Bs[soff(p, 0, r) + lk]),
                  Bh + (size_t)(j0 + r) * ldb + kk + lk);
            cpa16((u32)__cvta_generic_to_shared(&Bs[soff(p, 1, r) + lk]),
                  Bl + (size_t)(j0 + r) * ldb + kk + lk);
        }
        cpa_commit();
    }

    int idx = 0;
    for (int k0 = 0; k0 < K; k0 += 32, idx++) {
        int st = idx % 3;
        if (k0 + 32 < K) {
            cpa_wait1();
        } else {
            cpa_wait_all();
        }
        __syncthreads();

        int kn = k0 + 64;
        if (kn < K) {
            int sn = (idx + 2) % 3;
#pragma unroll
            for (int i = 0; i < 2; i++) {
                int r = lr + 32 * i;
                cpa16((u32)__cvta_generic_to_shared(&As[soff(sn, 0, r) + lk]),
                      Ah + (size_t)(i0 + r) * lda + kn + lk);
                cpa16((u32)__cvta_generic_to_shared(&As[soff(sn, 1, r) + lk]),
                      Al + (size_t)(i0 + r) * lda + kn + lk);
                cpa16((u32)__cvta_generic_to_shared(&Bs[soff(sn, 0, r) + lk]),
                      Bh + (size_t)(j0 + r) * ldb + kn + lk);
                cpa16((u32)__cvta_generic_to_shared(&Bs[soff(sn, 1, r) + lk]),
                      Bl + (size_t)(j0 + r) * ldb + kn + lk);
            }
            cpa_commit();
        }

#pragma unroll
        for (int ks = 0; ks < 2; ks++) {
            u32 af[2][2][4];
            u32 bq[2][4][2];
#pragma unroll
            for (int s = 0; s < 2; s++) {
#pragma unroll
                for (int mt = 0; mt < 2; mt++) {
                    int row = wm + mt * 16 + (lane & 15);
                    int col = ks * 16 + (lane >> 4) * 8;
                    u32 addr = (u32)__cvta_generic_to_shared(&As[soff(st, s, row) + col]);
                    u32 q0, q1, q2, q3;
                    ldsm4(q0, q1, q2, q3, addr);
                    af[s][mt][0] = q0;
                    af[s][mt][1] = q1;
                    af[s][mt][2] = q2;
                    af[s][mt][3] = q3;
                }
#pragma unroll
                for (int nt2 = 0; nt2 < 2; nt2++) {
                    int row = wn + nt2 * 16 + (lane & 7) + ((lane >> 4) << 3);
                    int col = ks * 16 + ((lane >> 3) & 1) * 8;
                    u32 addr = (u32)__cvta_generic_to_shared(&Bs[soff(st, s, row) + col]);
                    u32 q0, q1, q2, q3;
                    ldsm4(q0, q1, q2, q3, addr);
                    bq[s][nt2 * 2 + 0][0] = q0;
                    bq[s][nt2 * 2 + 0][1] = q1;
                    bq[s][nt2 * 2 + 1][0] = q2;
                    bq[s][nt2 * 2 + 1][1] = q3;
                }
            }
#pragma unroll
            for (int mt = 0; mt < 2; mt++) {
#pragma unroll
                for (int nt = 0; nt < 4; nt++) {
                    mma16816(acc[mt][nt][0], acc[mt][nt][1], acc[mt][nt][2], acc[mt][nt][3],
                             af[0][mt][0], af[0][mt][1], af[0][mt][2], af[0][mt][3],
                             bq[0][nt][0], bq[0][nt][1]);
                    mma16816(acc[mt][nt][0], acc[mt][nt][1], acc[mt][nt][2], acc[mt][nt][3],
                             af[0][mt][0], af[0][mt][1], af[0][mt][2], af[0][mt][3],
                             bq[1][nt][0], bq[1][nt][1]);
                    mma16816(acc[mt][nt][0], acc[mt][nt][1], acc[mt][nt][2], acc[mt][nt][3],
                             af[1][mt][0], af[1][mt][1], af[1][mt][2], af[1][mt][3],
                             bq[0][nt][0], bq[0][nt][1]);
                }
            }
        }
    }

#pragma unroll
    for (int mt = 0; mt < 2; mt++) {
#pragma unroll
        for (int nt = 0; nt < 4; nt++) {
#pragma unroll
            for (int rg = 0; rg < 2; rg++) {
                int row = i0 + wm + mt * 16 + (lane >> 2) + rg * 8;
                int col = j0 + wn + nt * 8 + 2 * (lane & 3);
                float v0 = alpha * acc[mt][nt][rg * 2 + 0];
                float v1 = alpha * acc[mt][nt][rg * 2 + 1];
                if (biasMode == 1) {
                    v0 += biasScale * bias[col];
                    v1 += biasScale * bias[col + 1];
                } else if (biasMode == 2) {
                    float bv = biasScale * bias[row];
                    v0 += bv;
                    v1 += bv;
                }
                size_t off = (size_t)row * ldc + col;
                if (Cf) {
                    *(float2*)(Cf + off) = make_float2(v0, v1);
                }
                if (Ch) {
                    bf16 h0 = __float2bfloat16(v0);
                    bf16 h1 = __float2bfloat16(v1);
                    __nv_bfloat162 ph;
                    ph.x = h0;
                    ph.y = h1;
                    __nv_bfloat162 pl;
                    pl.x = __float2bfloat16(v0 - __bfloat162float(h0));
                    pl.y = __float2bfloat16(v1 - __bfloat162float(h1));
                    *(__nv_bfloat162*)(Ch + off) = ph;
                    *(__nv_bfloat162*)(Cl + off) = pl;
                }
            }
        }
    }
}

// Fused Q/K/V projection GEMMs. blockIdx.z = batch*3 + id (id 0=Q,1=K,2=V).
__global__ void __launch_bounds__(128) qkv_gemm(
    const bf16* __restrict__ xavh, const bf16* __restrict__ xavl,
    const bf16* __restrict__ xsmh, const bf16* __restrict__ xsml,
    const bf16* __restrict__ wqh, const bf16* __restrict__ wql,
    const bf16* __restrict__ wkh, const bf16* __restrict__ wkl,
    const bf16* __restrict__ wvh, const bf16* __restrict__ wvl,
    bf16* __restrict__ Qh, bf16* __restrict__ Ql,
    bf16* __restrict__ Kh, bf16* __restrict__ Kl,
    bf16* __restrict__ VTh, bf16* __restrict__ VTl,
    const float* __restrict__ bq, const float* __restrict__ bk,
    const float* __restrict__ bv)
{
    extern __shared__ __align__(16) bf16 smbuf[];
    int z = blockIdx.z;
    int b = z / 3;
    int id = z - 3 * b;
    int bl = blockIdx.x;   // 0..31
    size_t xoff = (size_t)b * 131072;

    if (id == 0) {
        int j0 = (bl & 7) * 64;
        int i0 = (bl >> 3) * 64;
        gemm_core(smbuf, xavh + xoff, xavl + xoff, wqh, wql,
                  (float*)0, Qh + xoff, Ql + xoff,
                  512, 512, 512, 512, i0, j0, 1.f, bq, 1.f, 1);
    } else if (id == 1) {
        int j0 = (bl & 7) * 64;
        int i0 = (bl >> 3) * 64;
        gemm_core(smbuf, xavh + xoff, xavl + xoff, wkh, wkl,
                  (float*)0, Kh + xoff, Kl + xoff,
                  512, 512, 512, 512, i0, j0, 1.f, bk, 1.f, 1);
    } else {
        int j0 = (bl & 3) * 64;
        int i0 = (bl >> 2) * 64;
        gemm_core(smbuf, wvh, wvl, xsmh + xoff, xsml + xoff,
                  (float*)0, VTh + xoff, VTl + xoff,
                  512, 512, 512, 256, i0, j0, 1.f, bv, 16.f, 2);
    }
}

// Generic batched GEMM wrapper (logits, AV).
__global__ void __launch_bounds__(128) gemm_generic(
    const bf16* __restrict__ Ah, const bf16* __restrict__ Al,
    const bf16* __restrict__ Bh, const bf16* __restrict__ Bl,
    float* __restrict__ Cf,
    int K, int lda, int ldb, int ldc,
    long long sA, long long sB, long long sC, float alpha)
{
    extern __shared__ __align__(16) bf16 smbuf[];
    int b = blockIdx.z;
    gemm_core(smbuf, Ah + (size_t)b * sA, Al + (size_t)b * sA,
              Bh + (size_t)b * sB, Bl + (size_t)b * sB,
              Cf + (size_t)b * sC, (bf16*)0, (bf16*)0,
              K, lda, ldb, ldc, blockIdx.y * 64, blockIdx.x * 64,
              alpha, (const float*)0, 0.f, 0);
}

// x: (b,c,64,64) -> xavgT (b,c,256) block means, xsumT (b,c,256) group sums.
__global__ void __launch_bounds__(256) reduce_kernel(const float* __restrict__ x,
                                                     float* __restrict__ xavgT,
                                                     float* __restrict__ xsumT)
{
    int bc = blockIdx.x;
    const float4* xp = (const float4*)(x + (size_t)bc * 4096);
    int t = threadIdx.x;

    float4 v0 = xp[t * 4 + 0];
    float4 v1 = xp[t * 4 + 1];
    float4 v2 = xp[t * 4 + 2];
    float4 v3 = xp[t * 4 + 3];
    float s0 = v0.x + v0.y + v0.z + v0.w;
    float s1 = v1.x + v1.y + v1.z + v1.w;
    float s2 = v2.x + v2.y + v2.z + v2.w;
    float s3 = v3.x + v3.y + v3.z + v3.w;

    xsumT[(size_t)bc * 256 + t] = s0 + s1 + s2 + s3;

    __shared__ float sub[64][16];
    int r = t >> 2;
    int cb = (t & 3) * 4;
    sub[r][cb + 0] = s0;
    sub[r][cb + 1] = s1;
    sub[r][cb + 2] = s2;
    sub[r][cb + 3] = s3;
    __syncthreads();

    int bh = t >> 4;
    int bw = t & 15;
    float a = sub[4 * bh + 0][bw] + sub[4 * bh + 1][bw] +
              sub[4 * bh + 2][bw] + sub[4 * bh + 3][bw];
    xavgT[(size_t)bc * 256 + t] = a * 0.0625f;
}

// Both transposes in one launch: blockIdx.z = src*8 + b.
__global__ void transpose_split2(const float* __restrict__ in0,
                                 const float* __restrict__ in1,
                                 bf16* __restrict__ oh0, bf16* __restrict__ ol0,
                                 bf16* __restrict__ oh1, bf16* __restrict__ ol1)
{
    __shared__ float tile[32][33];
    int z = blockIdx.z;
    int b = z & 7;
    const float* in = (z < 8) ? in0 : in1;
    bf16* oh = (z < 8) ? oh0 : oh1;
    bf16* ol = (z < 8) ? ol0 : ol1;
    const float* ip = in + (size_t)b * 131072;
    size_t ob = (size_t)b * 131072;
    int n0 = blockIdx.x * 32;
    int c0 = blockIdx.y * 32;
    int tx = threadIdx.x;
    int ty = threadIdx.y;
#pragma unroll
    for (int q = 0; q < 4; q++)
        tile[ty + 8 * q][tx] = ip[(size_t)(c0 + ty + 8 * q) * 256 + n0 + tx];
    __syncthreads();
#pragma unroll
    for (int q = 0; q < 4; q++) {
        float v = tile[tx][ty + 8 * q];
        bf16 h = __float2bfloat16(v);
        size_t idx = ob + (size_t)(n0 + ty + 8 * q) * 512 + c0 + tx;
        oh[idx] = h;
        ol[idx] = __float2bfloat16(v - __bfloat162float(h));
    }
}

// All three weight splits in one launch; 2 float4 per thread.
__global__ void __launch_bounds__(256) split3_kernel(
    const float4* __restrict__ w0, const float4* __restrict__ w1,
    const float4* __restrict__ w2,
    uint2* __restrict__ o0h, uint2* __restrict__ o0l,
    uint2* __restrict__ o1h, uint2* __restrict__ o1l,
    uint2* __restrict__ o2h, uint2* __restrict__ o2l)
{
    int u = blockIdx.x * 256 + threadIdx.x;   // 0..98303
#pragma unroll
    for (int e = 0; e < 2; e++) {
        int i = u * 2 + e;                    // 0..196607 (float4 units)
        int which = i >> 16;                  // 65536 float4 per weight
        int j = i & 65535;
        const float4* in = (which == 0) ? w0 : (which == 1) ? w1 : w2;
        uint2* oh = (which == 0) ? o0h : (which == 1) ? o1h : o2h;
        uint2* ol = (which == 0) ? o0l : (which == 1) ? o1l : o2l;

        float4 v = in[j];
        bf16 h0 = __float2bfloat16(v.x);
        bf16 h1 = __float2bfloat16(v.y);
        bf16 h2 = __float2bfloat16(v.z);
        bf16 h3 = __float2bfloat16(v.w);
        __nv_bfloat162 p01;
        p01.x = h0;
        p01.y = h1;
        __nv_bfloat162 p23;
        p23.x = h2;
        p23.y = h3;
        uint2 ph;
        ph.x = *(u32*)&p01;
        ph.y = *(u32*)&p23;

        __nv_bfloat162 q01;
        q01.x = __float2bfloat16(v.x - __bfloat162float(h0));
        q01.y = __float2bfloat16(v.y - __bfloat162float(h1));
        __nv_bfloat162 q23;
        q23.x = __float2bfloat16(v.z - __bfloat162float(h2));
        q23.y = __float2bfloat16(v.w - __bfloat162float(h3));
        uint2 pl;
        pl.x = *(u32*)&q01;
        pl.y = *(u32*)&q23;

        oh[j] = ph;
        ol[j] = pl;
    }
}

// Row softmax over 256 elems, one warp per row; emits bf16 hi/lo probs.
__global__ void __launch_bounds__(256) softmax_kernel(const float* __restrict__ L,
                                                      bf16* __restrict__ Lh,
                                                      bf16* __restrict__ Ll)
{
    int row = blockIdx.x * 8 + (threadIdx.x >> 5);
    int lane = threadIdx.x & 31;
    const float* r = L + (size_t)row * 256;

    float xv[8];
#pragma unroll
    for (int k = 0; k < 8; k++) xv[k] = r[lane + 32 * k];

    float m = xv[0];
#pragma unroll
    for (int k = 1; k < 8; k++) m = fmaxf(m, xv[k]);
#pragma unroll
    for (int o = 16; o; o >>= 1) m = fmaxf(m, __shfl_xor_sync(0xffffffffu, m, o));

    float s = 0.f;
#pragma unroll
    for (int k = 0; k < 8; k++) {
        xv[k] = __expf(xv[k] - m);
        s += xv[k];
    }
#pragma unroll
    for (int o = 16; o; o >>= 1) s += __shfl_xor_sync(0xffffffffu, s, o);

    float inv = 1.f / s;
#pragma unroll
    for (int k = 0; k < 8; k++) {
        float p = xv[k] * inv;
        bf16 h = __float2bfloat16(p);
        size_t idx = (size_t)row * 256 + lane + 32 * k;
        Lh[idx] = h;
        Ll[idx] = __float2bfloat16(p - __bfloat162float(h));
    }
}

// out_small (b,n,c) -> out (b,c,64,64): 16 flat pixels per group, float4 writes.
__global__ void __launch_bounds__(256) broadcast_kernel(const float* __restrict__ os,
                                                        float4* __restrict__ out)
{
    int gi = blockIdx.x * 256 + threadIdx.x;
    int p4 = gi & 1023;
    int bc = gi >> 10;
    int b = bc >> 9;
    int c = bc & 511;
    int j = p4 >> 2;
    float v = os[((size_t)(b * 256 + j)) * 512 + c];
    out[gi] = make_float4(v, v, v, v);
}

extern "C" void kernel_launch(void* const* d_in, const int* in_sizes, int n_in,
                              void* d_out, int out_size)
{
    const float* x = (const float*)d_in[0];
    const float* Wq = (const float*)d_in[1];
    const float* bqv = (const float*)d_in[2];
    const float* Wk = (const float*)d_in[3];
    const float* bkv = (const float*)d_in[4];
    const float* Wv = (const float*)d_in[5];
    const float* bvv = (const float*)d_in[6];
    float* out = (float*)d_out;

    unsigned char* ar = 0;
    cudaGetSymbolAddress((void**)&ar, g_arena);

    float* xavgT = (float*)(ar + 0);
    float* xsumT = (float*)(ar + 4194304);
    bf16* xavh = (bf16*)(ar + 8388608);
    bf16* xavl = (bf16*)(ar + 10485760);
    bf16* xsmh = (bf16*)(ar + 12582912);
    bf16* xsml = (bf16*)(ar + 14680064);
    bf16* wqh = (bf16*)(ar + 16777216);
    bf16* wql = (bf16*)(ar + 17301504);
    bf16* wkh = (bf16*)(ar + 17825792);
    bf16* wkl = (bf16*)(ar + 18350080);
    bf16* wvh = (bf16*)(ar + 18874368);
    bf16* wvl = (bf16*)(ar + 19398656);
    bf16* Qh = (bf16*)(ar + 19922944);
    bf16* Ql = (bf16*)(ar + 22020096);
    bf16* Kh = (bf16*)(ar + 24117248);
    bf16* Kl = (bf16*)(ar + 26214400);
    bf16* VTh = (bf16*)(ar + 28311552);
    bf16* VTl = (bf16*)(ar + 30408704);
    float* Lf = (float*)(ar + 32505856);
    bf16* Lh = (bf16*)(ar + 34603008);
    bf16* Ll = (bf16*)(ar + 35651584);
    float* OS = (float*)(ar + 36700160);

    cudaFuncSetAttribute(qkv_gemm, cudaFuncAttributeMaxDynamicSharedMemorySize, 61440);
    cudaFuncSetAttribute(gemm_generic, cudaFuncAttributeMaxDynamicSharedMemorySize, 61440);

    reduce_kernel<<<4096, 256>>>(x, xavgT, xsumT);

    transpose_split2<<<dim3(8, 16, 16), dim3(32, 8)>>>(
        xavgT, xsumT, xavh, xavl, xsmh, xsml);

    split3_kernel<<<384, 256>>>(
        (const float4*)Wq, (const float4*)Wk, (const float4*)Wv,
        (uint2*)wqh, (uint2*)wql, (uint2*)wkh, (uint2*)wkl,
        (uint2*)wvh, (uint2*)wvl);

    qkv_gemm<<<dim3(32, 1, 24), 128, 61440>>>(
        xavh, xavl, xsmh, xsml,
        wqh, wql, wkh, wkl, wvh, wvl,
        Qh, Ql, Kh, Kl, VTh, VTl,
        bqv, bkv, bvv);

    gemm_generic<<<dim3(4, 4, 8), 128, 61440>>>(
        Qh, Ql, Kh, Kl, Lf,
        512, 512, 512, 256, 131072LL, 131072LL, 65536LL,
        0.044194173824159216f);

    softmax_kernel<<<256, 256>>>(Lf, Lh, Ll);

    gemm_generic<<<dim3(8, 4, 8), 128, 61440>>>(
        Lh, Ll, VTh, VTl, OS,
        256, 256, 256, 512, 65536LL, 131072LL, 131072LL, 1.f);

    broadcast_kernel<<<16384, 256>>>(OS, (float4*)out);
}

// round 15
// speedup vs baseline: 1.3617x; 1.3617x over previous
#include <cuda_runtime.h>
#include <cuda_fp16.h>

typedef unsigned int u32;

// Arena layout (bytes): xavgT f32 @0, xsumT f32 @4194304, xav f16 @8388608,
// xsm f16 @10485760, wq/wk/wv f16 @12582912/13107200/13631488,
// Q/K/VT f16 @14155776/16252928/18350080, Lf f32 @20447232, Lp f16 @22544384,
// OS f32 @23592960. End 27787264.
__device__ __align__(128) unsigned char g_arena[27787264];

__device__ __forceinline__ void ldsm4(u32& r0, u32& r1, u32& r2, u32& r3, u32 addr)
{
    asm volatile("ldmatrix.sync.aligned.m8n8.x4.shared.b16 { %0, %1, %2, %3 }, [%4];"
                 : "=r"(r0), "=r"(r1), "=r"(r2), "=r"(r3) : "r"(addr));
}

__device__ __forceinline__ void mma16816(float& d0, float& d1, float& d2, float& d3,
                                         u32 a0, u32 a1, u32 a2, u32 a3,
                                         u32 b0, u32 b1)
{
    asm volatile("mma.sync.aligned.m16n8k16.row.col.f32.f16.f16.f32 "
                 "{ %0, %1, %2, %3 }, { %4, %5, %6, %7 }, { %8, %9 }, { %0, %1, %2, %3 };"
                 : "+f"(d0), "+f"(d1), "+f"(d2), "+f"(d3)
                 : "r"(a0), "r"(a1), "r"(a2), "r"(a3), "r"(b0), "r"(b1));
}

__device__ __forceinline__ void cpa16(u32 dst, const half* src)
{
    asm volatile("cp.async.cg.shared.global [%0], [%1], 16;" :: "r"(dst), "l"(src));
}

__device__ __forceinline__ void cpa_commit()
{
    asm volatile("cp.async.commit_group;" ::: "memory");
}

__device__ __forceinline__ void cpa_wait_all()
{
    asm volatile("cp.async.wait_group 0;" ::: "memory");
}

// ---------------------------------------------------------------------------
// fp16 NT GEMM core: C = alpha * A B^T (+bias), fp32 accumulate.
// Tile 64x64, BK=32, 128 threads (4 warps 2x2), warp tile 32x32.
// 2-stage cp.async pipeline, static smem (20480 B).
// ---------------------------------------------------------------------------
__device__ __forceinline__ void gemm_core(
    const half* A, const half* B,
    float* Cf, half* Ch,
    int K, int lda, int ldb, int ldc, int i0, int j0,
    float alpha, const float* bias, float biasScale, int biasMode)
{
    __shared__ __align__(16) half As[2][64][40];
    __shared__ __align__(16) half Bs[2][64][40];

    const int t = threadIdx.x;
    const int lane = t & 31;
    const int wid = t >> 5;
    const int wm = (wid >> 1) * 32;
    const int wn = (wid & 1) * 32;

    float acc[2][4][4];
#pragma unroll
    for (int a = 0; a < 2; a++) {
#pragma unroll
        for (int b = 0; b < 4; b++) {
            acc[a][b][0] = 0.f;
            acc[a][b][1] = 0.f;
            acc[a][b][2] = 0.f;
            acc[a][b][3] = 0.f;
        }
    }

    const int lr = t >> 2;          // 0..31
    const int lk = (t & 3) * 8;     // 0,8,16,24

    // prologue: stage 0, k = 0
#pragma unroll
    for (int i = 0; i < 2; i++) {
        int r = lr + 32 * i;
        cpa16((u32)__cvta_generic_to_shared(&As[0][r][lk]), A + (size_t)(i0 + r) * lda + lk);
        cpa16((u32)__cvta_generic_to_shared(&Bs[0][r][lk]), B + (size_t)(j0 + r) * ldb + lk);
    }
    cpa_commit();

    for (int k0 = 0; k0 < K; k0 += 32) {
        cpa_wait_all();
        __syncthreads();
        int st = (k0 >> 5) & 1;
        int kn = k0 + 32;
        if (kn < K) {
            int sn = st ^ 1;
#pragma unroll
            for (int i = 0; i < 2; i++) {
                int r = lr + 32 * i;
                cpa16((u32)__cvta_generic_to_shared(&As[sn][r][lk]), A + (size_t)(i0 + r) * lda + kn + lk);
                cpa16((u32)__cvta_generic_to_shared(&Bs[sn][r][lk]), B + (size_t)(j0 + r) * ldb + kn + lk);
            }
            cpa_commit();
        }

#pragma unroll
        for (int ks = 0; ks < 2; ks++) {
            u32 af[2][4];
            u32 bq[4][2];
#pragma unroll
            for (int mt = 0; mt < 2; mt++) {
                int row = wm + mt * 16 + (lane & 15);
                int col = ks * 16 + (lane >> 4) * 8;
                u32 addr = (u32)__cvta_generic_to_shared(&As[st][row][col]);
                u32 q0, q1, q2, q3;
                ldsm4(q0, q1, q2, q3, addr);
                af[mt][0] = q0;
                af[mt][1] = q1;
                af[mt][2] = q2;
                af[mt][3] = q3;
            }
#pragma unroll
            for (int nt2 = 0; nt2 < 2; nt2++) {
                int row = wn + nt2 * 16 + (lane & 7) + ((lane >> 4) << 3);
                int col = ks * 16 + ((lane >> 3) & 1) * 8;
                u32 addr = (u32)__cvta_generic_to_shared(&Bs[st][row][col]);
                u32 q0, q1, q2, q3;
                ldsm4(q0, q1, q2, q3, addr);
                bq[nt2 * 2 + 0][0] = q0;
                bq[nt2 * 2 + 0][1] = q1;
                bq[nt2 * 2 + 1][0] = q2;
                bq[nt2 * 2 + 1][1] = q3;
            }
#pragma unroll
            for (int mt = 0; mt < 2; mt++) {
#pragma unroll
                for (int nt = 0; nt < 4; nt++) {
                    mma16816(acc[mt][nt][0], acc[mt][nt][1], acc[mt][nt][2], acc[mt][nt][3],
                             af[mt][0], af[mt][1], af[mt][2], af[mt][3],
                             bq[nt][0], bq[nt][1]);
                }
            }
        }
        __syncthreads();
    }

#pragma unroll
    for (int mt = 0; mt < 2; mt++) {
#pragma unroll
        for (int nt = 0; nt < 4; nt++) {
#pragma unroll
            for (int rg = 0; rg < 2; rg++) {
                int row = i0 + wm + mt * 16 + (lane >> 2) + rg * 8;
                int col = j0 + wn + nt * 8 + 2 * (lane & 3);
                float v0 = alpha * acc[mt][nt][rg * 2 + 0];
                float v1 = alpha * acc[mt][nt][rg * 2 + 1];
                if (biasMode == 1) {
                    v0 += biasScale * bias[col];
                    v1 += biasScale * bias[col + 1];
                } else if (biasMode == 2) {
                    float bv = biasScale * bias[row];
                    v0 += bv;
                    v1 += bv;
                }
                size_t off = (size_t)row * ldc + col;
                if (Cf) {
                    *(float2*)(Cf + off) = make_float2(v0, v1);
                }
                if (Ch) {
                    *(half2*)(Ch + off) = __floats2half2_rn(v0, v1);
                }
            }
        }
    }
}

// Fused Q/K/V projection GEMMs. blockIdx.z = batch*3 + id (id 0=Q,1=K,2=V).
__global__ void __launch_bounds__(128) qkv_gemm(
    const half* __restrict__ xav, const half* __restrict__ xsm,
    const half* __restrict__ wq, const half* __restrict__ wk,
    const half* __restrict__ wv,
    half* __restrict__ Q, half* __restrict__ Km, half* __restrict__ VT,
    const float* __restrict__ bq, const float* __restrict__ bk,
    const float* __restrict__ bv)
{
    int z = blockIdx.z;
    int b = z / 3;
    int id = z - 3 * b;
    int bl = blockIdx.x;   // 0..31
    size_t xoff = (size_t)b * 131072;

    if (id == 0) {
        int j0 = (bl & 7) * 64;
        int i0 = (bl >> 3) * 64;
        gemm_core(xav + xoff, wq, (float*)0, Q + xoff,
                  512, 512, 512, 512, i0, j0, 1.f, bq, 1.f, 1);
    } else if (id == 1) {
        int j0 = (bl & 7) * 64;
        int i0 = (bl >> 3) * 64;
        gemm_core(xav + xoff, wk, (float*)0, Km + xoff,
                  512, 512, 512, 512, i0, j0, 1.f, bk, 1.f, 1);
    } else {
        int j0 = (bl & 3) * 64;
        int i0 = (bl >> 2) * 64;
        gemm_core(wv, xsm + xoff, (float*)0, VT + xoff,
                  512, 512, 512, 256, i0, j0, 1.f, bv, 16.f, 2);
    }
}

// Generic batched GEMM wrapper (logits, AV) -> fp32 C.
__global__ void __launch_bounds__(128) gemm_generic(
    const half* __restrict__ A, const half* __restrict__ B,
    float* __restrict__ Cf,
    int K, int lda, int ldb, int ldc,
    long long sA, long long sB, long long sC, float alpha)
{
    int b = blockIdx.z;
    gemm_core(A + (size_t)b * sA, B + (size_t)b * sB,
              Cf + (size_t)b * sC, (half*)0,
              K, lda, ldb, ldc, blockIdx.y * 64, blockIdx.x * 64,
              alpha, (const float*)0, 0.f, 0);
}

// x: (b,c,64,64) -> xavgT (b,c,256) block means, xsumT (b,c,256) group sums.
__global__ void __launch_bounds__(256) reduce_kernel(const float* __restrict__ x,
                                                     float* __restrict__ xavgT,
                                                     float* __restrict__ xsumT)
{
    int bc = blockIdx.x;
    const float4* xp = (const float4*)(x + (size_t)bc * 4096);
    int t = threadIdx.x;

    float4 v0 = xp[t * 4 + 0];
    float4 v1 = xp[t * 4 + 1];
    float4 v2 = xp[t * 4 + 2];
    float4 v3 = xp[t * 4 + 3];
    float s0 = v0.x + v0.y + v0.z + v0.w;
    float s1 = v1.x + v1.y + v1.z + v1.w;
    float s2 = v2.x + v2.y + v2.z + v2.w;
    float s3 = v3.x + v3.y + v3.z + v3.w;

    xsumT[(size_t)bc * 256 + t] = s0 + s1 + s2 + s3;

    __shared__ float sub[64][16];
    int r = t >> 2;
    int cb = (t & 3) * 4;
    sub[r][cb + 0] = s0;
    sub[r][cb + 1] = s1;
    sub[r][cb + 2] = s2;
    sub[r][cb + 3] = s3;
    __syncthreads();

    int bh = t >> 4;
    int bw = t & 15;
    float a = sub[4 * bh + 0][bw] + sub[4 * bh + 1][bw] +
              sub[4 * bh + 2][bw] + sub[4 * bh + 3][bw];
    xavgT[(size_t)bc * 256 + t] = a * 0.0625f;
}

// Both transposes in one launch: blockIdx.z = src*8 + b. (b,c,n) f32 -> (b,n,c) f16.
__global__ void transpose_split2(const float* __restrict__ in0,
                                 const float* __restrict__ in1,
                                 half* __restrict__ o0, half* __restrict__ o1)
{
    __shared__ float tile[32][33];
    int z = blockIdx.z;
    int b = z & 7;
    const float* in = (z < 8) ? in0 : in1;
    half* oh = (z < 8) ? o0 : o1;
    const float* ip = in + (size_t)b * 131072;
    size_t ob = (size_t)b * 131072;
    int n0 = blockIdx.x * 32;
    int c0 = blockIdx.y * 32;
    int tx = threadIdx.x;
    int ty = threadIdx.y;
#pragma unroll
    for (int q = 0; q < 4; q++)
        tile[ty + 8 * q][tx] = ip[(size_t)(c0 + ty + 8 * q) * 256 + n0 + tx];
    __syncthreads();
#pragma unroll
    for (int q = 0; q < 4; q++) {
        float v = tile[tx][ty + 8 * q];
        size_t idx = ob + (size_t)(n0 + ty + 8 * q) * 512 + c0 + tx;
        oh[idx] = __float2half_rn(v);
    }
}

// All three weight conversions in one launch; 2 float4 per thread.
__global__ void __launch_bounds__(256) split3_kernel(
    const float4* __restrict__ w0, const float4* __restrict__ w1,
    const float4* __restrict__ w2,
    uint2* __restrict__ o0, uint2* __restrict__ o1, uint2* __restrict__ o2)
{
    int u = blockIdx.x * 256 + threadIdx.x;   // 0..98303
#pragma unroll
    for (int e = 0; e < 2; e++) {
        int i = u * 2 + e;                    // 0..196607 (float4 units)
        int which = i >> 16;                  // 65536 float4 per weight
        int j = i & 65535;
        const float4* in = (which == 0) ? w0 : (which == 1) ? w1 : w2;
        uint2* oh = (which == 0) ? o0 : (which == 1) ? o1 : o2;

        float4 v = in[j];
        half2 a = __floats2half2_rn(v.x, v.y);
        half2 b = __floats2half2_rn(v.z, v.w);
        uint2 p;
        p.x = *(u32*)&a;
        p.y = *(u32*)&b;
        oh[j] = p;
    }
}

// Row softmax over 256 elems, one warp per row; emits fp16 probs.
__global__ void __launch_bounds__(256) softmax_kernel(const float* __restrict__ L,
                                                      half* __restrict__ Lp)
{
    int row = blockIdx.x * 8 + (threadIdx.x >> 5);
    int lane = threadIdx.x & 31;
    const float* r = L + (size_t)row * 256;

    float xv[8];
#pragma unroll
    for (int k = 0; k < 8; k++) xv[k] = r[lane + 32 * k];

    float m = xv[0];
#pragma unroll
    for (int k = 1; k < 8; k++) m = fmaxf(m, xv[k]);
#pragma unroll
    for (int o = 16; o; o >>= 1) m = fmaxf(m, __shfl_xor_sync(0xffffffffu, m, o));

    float s = 0.f;
#pragma unroll
    for (int k = 0; k < 8; k++) {
        xv[k] = __expf(xv[k] - m);
        s += xv[k];
    }
#pragma unroll
    for (int o = 16; o; o >>= 1) s += __shfl_xor_sync(0xffffffffu, s, o);

    float inv = 1.f / s;
#pragma unroll
    for (int k = 0; k < 8; k++) {
        float p = xv[k] * inv;
        Lp[(size_t)row * 256 + lane + 32 * k] = __float2half_rn(p);
    }
}

// out_small (b,n,c) -> out (b,c,64,64): 16 flat pixels per group, float4 writes.
__global__ void __launch_bounds__(256) broadcast_kernel(const float* __restrict__ os,
                                                        float4* __restrict__ out)
{
    int gi = blockIdx.x * 256 + threadIdx.x;
    int p4 = gi & 1023;
    int bc = gi >> 10;
    int b = bc >> 9;
    int c = bc & 511;
    int j = p4 >> 2;
    float v = os[((size_t)(b * 256 + j)) * 512 + c];
    out[gi] = make_float4(v, v, v, v);
}

extern "C" void kernel_launch(void* const* d_in, const int* in_sizes, int n_in,
                              void* d_out, int out_size)
{
    const float* x = (const float*)d_in[0];
    const float* Wq = (const float*)d_in[1];
    const float* bqv = (const float*)d_in[2];
    const float* Wk = (const float*)d_in[3];
    const float* bkv = (const float*)d_in[4];
    const float* Wv = (const float*)d_in[5];
    const float* bvv = (const float*)d_in[6];
    float* out = (float*)d_out;

    unsigned char* ar = 0;
    cudaGetSymbolAddress((void**)&ar, g_arena);

    float* xavgT = (float*)(ar + 0);
    float* xsumT = (float*)(ar + 4194304);
    half* xav = (half*)(ar + 8388608);
    half* xsm = (half*)(ar + 10485760);
    half* wq = (half*)(ar + 12582912);
    half* wk = (half*)(ar + 13107200);
    half* wv = (half*)(ar + 13631488);
    half* Q = (half*)(ar + 14155776);
    half* Km = (half*)(ar + 16252928);
    half* VT = (half*)(ar + 18350080);
    float* Lf = (float*)(ar + 20447232);
    half* Lp = (half*)(ar + 22544384);
    float* OS = (float*)(ar + 23592960);

    reduce_kernel<<<4096, 256>>>(x, xavgT, xsumT);

    transpose_split2<<<dim3(8, 16, 16), dim3(32, 8)>>>(xavgT, xsumT, xav, xsm);

    split3_kernel<<<384, 256>>>(
        (const float4*)Wq, (const float4*)Wk, (const float4*)Wv,
        (uint2*)wq, (uint2*)wk, (uint2*)wv);

    qkv_gemm<<<dim3(32, 1, 24), 128>>>(
        xav, xsm, wq, wk, wv, Q, Km, VT, bqv, bkv, bvv);

    gemm_generic<<<dim3(4, 4, 8), 128>>>(
        Q, Km, Lf,
        512, 512, 512, 256, 131072LL, 131072LL, 65536LL,
        0.044194173824159216f);

    softmax_kernel<<<256, 256>>>(Lf, Lp);

    gemm_generic<<<dim3(8, 4, 8), 128>>>(
        Lp, VT, OS,
        256, 256, 256, 512, 65536LL, 131072LL, 131072LL, 1.f);

    broadcast_kernel<<<16384, 256>>>(OS, (float4*)out);
}